// round 14
// baseline (speedup 1.0000x reference)
#include <cuda_runtime.h>
#include <cuda_bf16.h>

#define N_NODES 131072
#define NG      4096        // graphs
#define NPG     32          // nodes per graph
#define NE      1048576     // edges per branch
#define SDIM    64
#define HDIM    128
#define CAP     64          // bucket capacity per (branch, graph)

#define EPT     8                        // edges per thread in k1
#define NB_EDGE ((2 * NE) / (256 * EPT)) // 1024 edge-filter blocks
#define NB_FOLD 32                       // fold blocks appended to k1 grid
#define GPB     8                        // graphs per k2 block

// ---------------- scratch (device globals; zero-initialized at load) --------
// Invariant: g_cnt is all-zero before every k1 launch. Initially true (module
// load zero-init); maintained because k2 re-zeroes every counter it reads.
__device__ int   g_cnt[2][NG];
__device__ int   g_bucket[2][NG][CAP];
__device__ float g_wsd[2][2][SDIM];     // [branch][{src,dst}][s] : folded W@att

// ---------------- K1: edge filter + (in extra blocks) W@att fold ------------
__global__ void k1_filter(const int* __restrict__ upE, const int* __restrict__ dnE,
                          int is64_up, int is64_dn,
                          const float* __restrict__ upW, const float* __restrict__ upAs,
                          const float* __restrict__ upAd,
                          const float* __restrict__ dnW, const float* __restrict__ dnAs,
                          const float* __restrict__ dnAd) {
    if (blockIdx.x >= NB_EDGE) {
        // fold: one warp per output scalar w[b][v][s] = sum_h W[s,h]*att[h]
        int w = (blockIdx.x - NB_EDGE) * 8 + (threadIdx.x >> 5);  // 0..255
        int l = threadIdx.x & 31;
        int b = w >> 7;
        int v = (w >> 6) & 1;
        int s = w & 63;
        const float* W = b ? dnW : upW;
        const float* a = b ? (v ? dnAd : dnAs) : (v ? upAd : upAs);
        float4 wv = ((const float4*)(W + s * HDIM))[l];
        float4 av = ((const float4*)a)[l];
        float acc = wv.x * av.x + wv.y * av.y + wv.z * av.z + wv.w * av.w;
        #pragma unroll
        for (int o = 16; o; o >>= 1) acc += __shfl_xor_sync(0xffffffffu, acc, o);
        if (l == 0) g_wsd[b][v][s] = acc;
        return;
    }

    // edge filter: EPT=8 edges per thread, wide dst-scan loads (high MLP)
    long long t = (long long)blockIdx.x * blockDim.x + threadIdx.x;
    long long e8 = t * EPT;
    int b = (e8 >= NE) ? 1 : 0;          // blocks never straddle the branch
    long long e = e8 - (long long)b * NE;
    const int* p = b ? dnE : upE;
    int is64 = b ? is64_dn : is64_up;

    int d[EPT];
    if (is64) {
        const int4* q = (const int4*)(p + 2 * (NE + e));  // 8 edges = 64B
        #pragma unroll
        for (int j = 0; j < 4; j++) {
            int4 a = q[j];
            d[2 * j]     = a.x;
            d[2 * j + 1] = a.z;
        }
    } else {
        const int4* q = (const int4*)(p + NE + e);        // 8 edges = 32B
        #pragma unroll
        for (int j = 0; j < 2; j++) {
            int4 a = q[j];
            d[4 * j]     = a.x;
            d[4 * j + 1] = a.y;
            d[4 * j + 2] = a.z;
            d[4 * j + 3] = a.w;
        }
    }

    int stride = is64 ? 2 : 1;
    #pragma unroll
    for (int k = 0; k < EPT; k++) {
        if ((d[k] & 31) == 31) {
            int g = d[k] >> 5;
            int src = p[(e + k) * stride];
            int pos = atomicAdd(&g_cnt[b][g], 1);
            if (pos < CAP) g_bucket[b][g][pos] = src;
        }
    }
}

// ---------------- K2: fused. 16 agg warps (half-warp edge pairing) +
// s-split batched GEMV over all 512 threads + fused epilogue. ---------------
__global__ __launch_bounds__(512, 4) void k2_fused(
    const float* __restrict__ upx, const float* __restrict__ dnx,
    const float* __restrict__ upW, const float* __restrict__ dnW,
    const float* __restrict__ upB, const float* __restrict__ dnB,
    const float* __restrict__ mlpW, const float* __restrict__ mlpB,
    float* __restrict__ out) {

    int g0 = blockIdx.x * GPB;
    int t  = threadIdx.x;
    int w  = t >> 5;
    int l  = t & 31;

    __shared__ int   sh_src[16][CAP];        // 4KB
    __shared__ float xt[2][SDIM][GPB];       // 4KB transposed xagg
    __shared__ float ph[2][GPB][HDIM];       // 8KB GEMV partials (s-half 1)
    __shared__ float sig[2][GPB][HDIM];      // 8KB sigmoid outputs

    // ---- phase 1: aggregation. Half-warp edge pairing: lanes 0-15 = edge A,
    // lanes 16-31 = edge B; lane owns 4 dims (float4). Per 2 edges:
    // 1 LDG.128, 1 LDS, 4 SHFL (vs 2 LDG + 2 LDS + 10 SHFL before). ----
    {
        int b  = w >> 3;                     // warps 0-7: up, 8-15: down
        int gi = w & 7;
        int g  = g0 + gi;
        const float* x = b ? dnx : upx;
        int hl = l >> 4;                     // which edge of the pair
        int q  = l & 15;                     // lane within half: dims 4q..4q+3

        int n = g_cnt[b][g];
        if (l == 0) g_cnt[b][g] = 0;         // restore zero-invariant
        if (n > CAP) n = CAP;
        ((int2*)sh_src[w])[l] = ((const int2*)g_bucket[b][g])[l];
        __syncwarp();

        float4 ws4 = ((const float4*)g_wsd[b][0])[q];

        // a_dst (both halves compute identically; 4-deep reduce in-half)
        float a_dst;
        {
            float4 wd4 = ((const float4*)g_wsd[b][1])[q];
            float4 xd = ((const float4*)(x + (g * NPG + NPG - 1) * SDIM))[q];
            float pd = xd.x * wd4.x + xd.y * wd4.y + xd.z * wd4.z + xd.w * wd4.w;
            #pragma unroll
            for (int o = 8; o; o >>= 1) pd += __shfl_xor_sync(0xffffffffu, pd, o);
            a_dst = pd;
        }

        // un-shifted softmax aggregation (logits O(10); exp safe in fp32)
        float denom = 0.f;
        float4 acc = make_float4(0.f, 0.f, 0.f, 0.f);
        for (int base = 0; base < n; base += 2) {
            int idx = base + hl;
            bool valid = idx < n;
            int src = sh_src[w][valid ? idx : base];
            float4 xv = ((const float4*)(x + src * SDIM))[q];
            float ps = xv.x * ws4.x + xv.y * ws4.y + xv.z * ws4.z + xv.w * ws4.w;
            #pragma unroll
            for (int o = 8; o; o >>= 1) ps += __shfl_xor_sync(0xffffffffu, ps, o);
            float ev = ps + a_dst;
            ev = ev > 0.f ? ev : 0.2f * ev;  // leaky_relu(0.2)
            float qe = valid ? __expf(ev) : 0.f;
            denom += qe;
            acc.x += qe * xv.x;
            acc.y += qe * xv.y;
            acc.z += qe * xv.z;
            acc.w += qe * xv.w;
        }
        // combine the two halves (they hold the same dims, different edges)
        denom += __shfl_xor_sync(0xffffffffu, denom, 16);
        acc.x += __shfl_xor_sync(0xffffffffu, acc.x, 16);
        acc.y += __shfl_xor_sync(0xffffffffu, acc.y, 16);
        acc.z += __shfl_xor_sync(0xffffffffu, acc.z, 16);
        acc.w += __shfl_xor_sync(0xffffffffu, acc.w, 16);
        float inv = 1.f / (denom + 1e-16f);
        if (hl == 0) {                       // lanes 0-15 write dims 4q..4q+3
            xt[b][4 * q + 0][gi] = acc.x * inv;
            xt[b][4 * q + 1][gi] = acc.y * inv;
            xt[b][4 * q + 2][gi] = acc.z * inv;
            xt[b][4 * q + 3][gi] = acc.w * inv;
        }
    }
    __syncthreads();

    // ---- phase 2: batched GEMV split over ALL 512 threads.
    // thread = (s-half, branch, h); each W element FMAed against 8 graphs. ----
    {
        int sh = t >> 8;                     // s half: 0 or 1
        int r  = t & 255;
        int b  = r >> 7;
        int h  = r & 127;
        const float* W = b ? dnW : upW;

        float ho[GPB];
        #pragma unroll
        for (int gi = 0; gi < GPB; gi++) ho[gi] = 0.f;

        int s0 = sh * (SDIM / 2);
        #pragma unroll 8
        for (int s = s0; s < s0 + SDIM / 2; s++) {
            float wv = W[s * HDIM + h];               // coalesced
            float4 xa = *(const float4*)&xt[b][s][0]; // broadcast LDS
            float4 xb = *(const float4*)&xt[b][s][4];
            ho[0] += wv * xa.x; ho[1] += wv * xa.y;
            ho[2] += wv * xa.z; ho[3] += wv * xa.w;
            ho[4] += wv * xb.x; ho[5] += wv * xb.y;
            ho[6] += wv * xb.z; ho[7] += wv * xb.w;
        }
        if (sh == 1) {
            #pragma unroll
            for (int gi = 0; gi < GPB; gi++) ph[b][gi][h] = ho[gi];
        }
        __syncthreads();
        if (sh == 0) {
            float bv = (b ? dnB : upB)[h];
            #pragma unroll
            for (int gi = 0; gi < GPB; gi++)
                sig[b][gi][h] = 1.f / (1.f + __expf(-(ho[gi] + ph[b][gi][h] + bv)));
        }
    }
    __syncthreads();

    // ---- phase 3: fused epilogue, warps 0..7 -> graph g0+w ----
    if (w < GPB) {
        float4 s0 = ((const float4*)sig[0][w])[l];
        float4 s1 = ((const float4*)sig[1][w])[l];
        float4 mw = ((const float4*)mlpW)[l];
        float s = s0.x * s1.x * mw.x + s0.y * s1.y * mw.y
                + s0.z * s1.z * mw.z + s0.w * s1.w * mw.w;
        #pragma unroll
        for (int o = 16; o; o >>= 1) s += __shfl_xor_sync(0xffffffffu, s, o);
        if (l == 0) out[g0 + w] = s + mlpB[0];
    }
}

// ---------------- launch ----------------------------------------------------
extern "C" void kernel_launch(void* const* d_in, const int* in_sizes, int n_in,
                              void* d_out, int out_size) {
    const float* up_x  = (const float*)d_in[0];
    const int*   up_e  = (const int*)  d_in[1];
    const float* dn_x  = (const float*)d_in[3];
    const int*   dn_e  = (const int*)  d_in[4];
    const float* upW   = (const float*)d_in[6];
    const float* upAs  = (const float*)d_in[7];
    const float* upAd  = (const float*)d_in[8];
    const float* upB   = (const float*)d_in[9];
    const float* dnW   = (const float*)d_in[10];
    const float* dnAs  = (const float*)d_in[11];
    const float* dnAd  = (const float*)d_in[12];
    const float* dnB   = (const float*)d_in[13];
    const float* mlpW  = (const float*)d_in[14];
    const float* mlpB  = (const float*)d_in[15];
    float* out = (float*)d_out;

    // int64 edge tensors arrive as int32 words with doubled element count:
    // 2*2*NE = 4*NE words vs 2*NE for true int32.
    int is64_up = (in_sizes[1] >= 4 * NE) ? 1 : 0;
    int is64_dn = (in_sizes[4] >= 4 * NE) ? 1 : 0;

    k1_filter<<<NB_EDGE + NB_FOLD, 256>>>(up_e, dn_e, is64_up, is64_dn,
                                          upW, upAs, upAd, dnW, dnAs, dnAd);
    k2_fused<<<NG / GPB, 512>>>(up_x, dn_x, upW, dnW, upB, dnB, mlpW, mlpB, out);
}